// round 4
// baseline (speedup 1.0000x reference)
#include <cuda_runtime.h>
#include <cuda_bf16.h>

#define N_NODES 50000
#define N_EDGES 1600000
#define C_OUT   256
#define SCAN_BLOCKS 196   // ceil(50000/256)

// ---------------- scratch (static device globals; allocation-free) ----------
__device__ int   g_is64;
__device__ int   g_src[N_EDGES];
__device__ int   g_dst[N_EDGES];
__device__ float g_ew[N_EDGES];
__device__ int   g_srcS[N_EDGES];
__device__ float g_ewS[N_EDGES];
__device__ int   g_deg[N_NODES];
__device__ int   g_blkoff[SCAN_BLOCKS];
__device__ int   g_rowoff[N_NODES + 1];
__device__ int   g_cursor[N_NODES];
__device__ float g_agg[(size_t)N_NODES * C_OUT];
__device__ float g_h[(size_t)N_NODES * C_OUT];

// packed 2-lane fp32 fma: d = a*b + d  (per-lane IEEE fp32, Blackwell FFMA2)
__device__ __forceinline__ void ffma2(unsigned long long& d,
                                      unsigned long long a,
                                      unsigned long long b) {
    asm("fma.rn.f32x2 %0, %1, %2, %0;" : "+l"(d) : "l"(a), "l"(b));
}

// ---------------- int64-vs-int32 edge_index detection -----------------------
__global__ void detect_kernel(const int* __restrict__ ei_words) {
    __shared__ int nz;
    if (threadIdx.x == 0) nz = 0;
    __syncthreads();
    if (ei_words[2 * threadIdx.x + 1] != 0) atomicOr(&nz, 1);
    __syncthreads();
    if (threadIdx.x == 0) g_is64 = (nz == 0) ? 1 : 0;
}

// decode edge_index, compute ew = mean(edge_attr, -1), histogram dst degrees
__global__ void build_edges_kernel(const int* __restrict__ ei,
                                   const float* __restrict__ ea) {
    int e = blockIdx.x * blockDim.x + threadIdx.x;
    if (e >= N_EDGES) return;
    int s, d;
    if (g_is64) {
        s = ei[2 * (size_t)e];
        d = ei[2 * (size_t)N_EDGES + 2 * (size_t)e];
    } else {
        s = ei[e];
        d = ei[N_EDGES + e];
    }
    g_src[e] = s;
    g_dst[e] = d;
    const float4* a4 = (const float4*)(ea + (size_t)e * 8);
    float4 u = a4[0];
    float4 v = a4[1];
    g_ew[e] = (u.x + u.y + u.z + u.w + v.x + v.y + v.z + v.w) * 0.125f;
    atomicAdd(&g_deg[d], 1);
}

// ---------------- decoupled 3-phase exclusive scan ---------------------------
__global__ void scan_p1_kernel() {
    int i = blockIdx.x * 256 + threadIdx.x;
    int v = (i < N_NODES) ? g_deg[i] : 0;
#pragma unroll
    for (int o = 16; o > 0; o >>= 1) v += __shfl_down_sync(~0u, v, o);
    __shared__ int ws[8];
    int lane = threadIdx.x & 31, wid = threadIdx.x >> 5;
    if (lane == 0) ws[wid] = v;
    __syncthreads();
    if (threadIdx.x == 0) {
        int s = 0;
#pragma unroll
        for (int w = 0; w < 8; w++) s += ws[w];
        g_blkoff[blockIdx.x] = s;
    }
}

__global__ void scan_p2_kernel() {
    int tid = threadIdx.x;  // 256 threads
    int v = (tid < SCAN_BLOCKS) ? g_blkoff[tid] : 0;
    int lane = tid & 31, wid = tid >> 5;
    int x = v;
#pragma unroll
    for (int o = 1; o < 32; o <<= 1) {
        int t = __shfl_up_sync(~0u, x, o);
        if (lane >= o) x += t;
    }
    __shared__ int ws[8];
    if (lane == 31) ws[wid] = x;
    __syncthreads();
    if (wid == 0 && lane < 8) {
        int w = ws[lane];
#pragma unroll
        for (int o = 1; o < 8; o <<= 1) {
            int t = __shfl_up_sync(0xffu, w, o);
            if (lane >= o) w += t;
        }
        ws[lane] = w;
    }
    __syncthreads();
    int excl = (x - v) + (wid > 0 ? ws[wid - 1] : 0);
    if (tid < SCAN_BLOCKS) g_blkoff[tid] = excl;
    if (tid == 0) g_rowoff[N_NODES] = N_EDGES;
}

__global__ void scan_p3_kernel() {
    int i = blockIdx.x * 256 + threadIdx.x;
    int v = (i < N_NODES) ? g_deg[i] : 0;
    int lane = threadIdx.x & 31, wid = threadIdx.x >> 5;
    int x = v;
#pragma unroll
    for (int o = 1; o < 32; o <<= 1) {
        int t = __shfl_up_sync(~0u, x, o);
        if (lane >= o) x += t;
    }
    __shared__ int ws[8];
    if (lane == 31) ws[wid] = x;
    __syncthreads();
    if (wid == 0 && lane < 8) {
        int w = ws[lane];
#pragma unroll
        for (int o = 1; o < 8; o <<= 1) {
            int t = __shfl_up_sync(0xffu, w, o);
            if (lane >= o) w += t;
        }
        ws[lane] = w;
    }
    __syncthreads();
    int excl = (x - v) + (wid > 0 ? ws[wid - 1] : 0) + g_blkoff[blockIdx.x];
    if (i < N_NODES) {
        g_rowoff[i] = excl;
        g_cursor[i] = excl;
    }
}

// scatter edges into CSR buckets (sorted by dst)
__global__ void fill_kernel() {
    int e = blockIdx.x * blockDim.x + threadIdx.x;
    if (e >= N_EDGES) return;
    int d = g_dst[e];
    int p = atomicAdd(&g_cursor[d], 1);
    g_srcS[p] = g_src[e];
    g_ewS[p] = g_ew[e];
}

// ---------------- gather-aggregate: out[i] = sum_{e: dst=i} in[src_e] * w_e --
template <int C, bool USE_W>
__global__ void gather_kernel(const float* __restrict__ in,
                              float* __restrict__ out) {
    constexpr int L = C / 4;        // lanes per node
    constexpr int G = 256 / L;      // nodes per 256-thread block
    int grp  = threadIdx.x / L;
    int lane = threadIdx.x % L;
    int node = blockIdx.x * G + grp;
    if (node >= N_NODES) return;

    int e0 = g_rowoff[node];
    int e1 = g_rowoff[node + 1];
    const float4* in4 = (const float4*)in;
    float4 acc = make_float4(0.f, 0.f, 0.f, 0.f);

    int e = e0;
    for (; e + 4 <= e1; e += 4) {
        int s0 = g_srcS[e], s1 = g_srcS[e + 1];
        int s2 = g_srcS[e + 2], s3 = g_srcS[e + 3];
        float w0 = USE_W ? g_ewS[e] : 1.0f;
        float w1 = USE_W ? g_ewS[e + 1] : 1.0f;
        float w2 = USE_W ? g_ewS[e + 2] : 1.0f;
        float w3 = USE_W ? g_ewS[e + 3] : 1.0f;
        float4 v0 = in4[(size_t)s0 * L + lane];
        float4 v1 = in4[(size_t)s1 * L + lane];
        float4 v2 = in4[(size_t)s2 * L + lane];
        float4 v3 = in4[(size_t)s3 * L + lane];
        acc.x = fmaf(v0.x, w0, acc.x); acc.y = fmaf(v0.y, w0, acc.y);
        acc.z = fmaf(v0.z, w0, acc.z); acc.w = fmaf(v0.w, w0, acc.w);
        acc.x = fmaf(v1.x, w1, acc.x); acc.y = fmaf(v1.y, w1, acc.y);
        acc.z = fmaf(v1.z, w1, acc.z); acc.w = fmaf(v1.w, w1, acc.w);
        acc.x = fmaf(v2.x, w2, acc.x); acc.y = fmaf(v2.y, w2, acc.y);
        acc.z = fmaf(v2.z, w2, acc.z); acc.w = fmaf(v2.w, w2, acc.w);
        acc.x = fmaf(v3.x, w3, acc.x); acc.y = fmaf(v3.y, w3, acc.y);
        acc.z = fmaf(v3.z, w3, acc.z); acc.w = fmaf(v3.w, w3, acc.w);
    }
    for (; e < e1; e++) {
        int sa = g_srcS[e];
        float wa = USE_W ? g_ewS[e] : 1.0f;
        float4 va = in4[(size_t)sa * L + lane];
        acc.x = fmaf(va.x, wa, acc.x); acc.y = fmaf(va.y, wa, acc.y);
        acc.z = fmaf(va.z, wa, acc.z); acc.w = fmaf(va.w, wa, acc.w);
    }
    ((float4*)out)[(size_t)node * L + lane] = acc;
}

// ---------------- GEMM: out[M,256] = A[M,K] @ W[256,K]^T + epilogue ---------
// BM=BN=64, BK=16, 256 threads, 4x4 register tile, packed f32x2 FMAs.
// A tile stored pre-duplicated (a,a) so f32x2 operands need no per-k packing:
// per k-step: 2x LDS.128 (A-dup) + 1x LDS.128 (B pairs) + 8 FFMA2 = 11 issues
// for 16 FMAs (vs 18 issues for scalar FFMA).
template <int K, bool BN_RELU>
__global__ void gemm_kernel(const float* __restrict__ A,
                            const float* __restrict__ W,
                            const float* __restrict__ bias,
                            const float* __restrict__ gam,
                            const float* __restrict__ bet,
                            const float* __restrict__ mu,
                            const float* __restrict__ var,
                            float* __restrict__ out) {
    constexpr int BM = 64, BN = 64, BK = 16;
    __shared__ __align__(16) float2 As2[BK][BM];   // duplicated A: (a,a)
    __shared__ __align__(16) float  Bs[BK][BN];

    int m0 = blockIdx.x * BM;
    int n0 = blockIdx.y * BN;
    int tid = threadIdx.x;
    int tx = tid % 16;   // output col group (4 cols)
    int ty = tid / 16;   // output row group (4 rows)

    int lr = tid / 4;          // 0..63 : tile row (A) / weight row n (B)
    int lk = (tid % 4) * 4;    // 0,4,8,12 : k offset

    unsigned long long acc2[4][2];
#pragma unroll
    for (int i = 0; i < 4; i++) {
        acc2[i][0] = 0ull;
        acc2[i][1] = 0ull;
    }

    for (int k0 = 0; k0 < K; k0 += BK) {
        {
            int row = m0 + lr;
            float4 v = make_float4(0.f, 0.f, 0.f, 0.f);
            if (row < N_NODES)
                v = *(const float4*)(A + (size_t)row * K + k0 + lk);
            As2[lk + 0][lr] = make_float2(v.x, v.x);
            As2[lk + 1][lr] = make_float2(v.y, v.y);
            As2[lk + 2][lr] = make_float2(v.z, v.z);
            As2[lk + 3][lr] = make_float2(v.w, v.w);

            float4 w = *(const float4*)(W + (size_t)(n0 + lr) * K + k0 + lk);
            Bs[lk + 0][lr] = w.x;
            Bs[lk + 1][lr] = w.y;
            Bs[lk + 2][lr] = w.z;
            Bs[lk + 3][lr] = w.w;
        }
        __syncthreads();
#pragma unroll
        for (int k = 0; k < BK; k++) {
            // A duplicates: 4 x u64 = 2 x LDS.128
            ulonglong2 aA = *(const ulonglong2*)&As2[k][ty * 4];     // (a0,a0),(a1,a1)
            ulonglong2 aB = *(const ulonglong2*)&As2[k][ty * 4 + 2]; // (a2,a2),(a3,a3)
            // B natural pairs: 1 x LDS.128 -> (b0,b1),(b2,b3)
            ulonglong2 bb = *(const ulonglong2*)&Bs[k][tx * 4];
            ffma2(acc2[0][0], aA.x, bb.x); ffma2(acc2[0][1], aA.x, bb.y);
            ffma2(acc2[1][0], aA.y, bb.x); ffma2(acc2[1][1], aA.y, bb.y);
            ffma2(acc2[2][0], aB.x, bb.x); ffma2(acc2[2][1], aB.x, bb.y);
            ffma2(acc2[3][0], aB.y, bb.x); ffma2(acc2[3][1], aB.y, bb.y);
        }
        __syncthreads();
    }

    // epilogue: +bias, optional BN(eval)+ReLU, float4 store
    int nbase = n0 + tx * 4;
    float bb4[4], ss[4], tt[4];
#pragma unroll
    for (int j = 0; j < 4; j++) {
        bb4[j] = bias[nbase + j];
        if (BN_RELU) {
            float inv = gam[nbase + j] * rsqrtf(var[nbase + j] + 1e-5f);
            ss[j] = inv;
            tt[j] = bet[nbase + j] - mu[nbase + j] * inv;
        }
    }
#pragma unroll
    for (int i = 0; i < 4; i++) {
        int m = m0 + ty * 4 + i;
        if (m < N_NODES) {
            float2 p0 = *(float2*)&acc2[i][0];
            float2 p1 = *(float2*)&acc2[i][1];
            float a4[4] = {p0.x, p0.y, p1.x, p1.y};
            float z[4];
#pragma unroll
            for (int j = 0; j < 4; j++) {
                float v = a4[j] + bb4[j];
                if (BN_RELU) v = fmaxf(fmaf(v, ss[j], tt[j]), 0.f);
                z[j] = v;
            }
            *(float4*)(out + (size_t)m * C_OUT + nbase) =
                make_float4(z[0], z[1], z[2], z[3]);
        }
    }
}

// ---------------- launch ----------------------------------------------------
extern "C" void kernel_launch(void* const* d_in, const int* in_sizes, int n_in,
                              void* d_out, int out_size) {
    const float* x   = (const float*)d_in[0];
    const int*   ei  = (const int*)d_in[1];
    const float* ea  = (const float*)d_in[2];
    const float* W1  = (const float*)d_in[3];
    const float* b1  = (const float*)d_in[4];
    const float* g1  = (const float*)d_in[5];
    const float* be1 = (const float*)d_in[6];
    const float* m1  = (const float*)d_in[7];
    const float* v1  = (const float*)d_in[8];
    const float* W2  = (const float*)d_in[9];
    const float* b2  = (const float*)d_in[10];
    const float* g2  = (const float*)d_in[11];
    const float* be2 = (const float*)d_in[12];
    const float* m2  = (const float*)d_in[13];
    const float* v2  = (const float*)d_in[14];
    const float* W3  = (const float*)d_in[15];
    const float* b3  = (const float*)d_in[16];
    float* out = (float*)d_out;

    void *p_agg, *p_h, *p_deg;
    cudaGetSymbolAddress(&p_agg, g_agg);
    cudaGetSymbolAddress(&p_h, g_h);
    cudaGetSymbolAddress(&p_deg, g_deg);
    float* agg = (float*)p_agg;
    float* h   = (float*)p_h;

    // ---- CSR build (once, reused by all 3 layers) ----
    detect_kernel<<<1, 64>>>(ei);
    cudaMemsetAsync(p_deg, 0, N_NODES * sizeof(int));
    build_edges_kernel<<<(N_EDGES + 255) / 256, 256>>>(ei, ea);
    scan_p1_kernel<<<SCAN_BLOCKS, 256>>>();
    scan_p2_kernel<<<1, 256>>>();
    scan_p3_kernel<<<SCAN_BLOCKS, 256>>>();
    fill_kernel<<<(N_EDGES + 255) / 256, 256>>>();

    dim3 ggrid(782, 4);  // ceil(50000/64) x (256/64), BM=BN=64

    // ---- layer 1: aggregate x (C=128), GEMM K=128 + BN1 + ReLU ----
    gather_kernel<128, true><<<(N_NODES + 7) / 8, 256>>>(x, agg);
    gemm_kernel<128, true><<<ggrid, 256>>>(agg, W1, b1, g1, be1, m1, v1, h);

    // ---- layer 2: aggregate h (C=256), GEMM K=256 + BN2 + ReLU ----
    gather_kernel<256, true><<<(N_NODES + 3) / 4, 256>>>(h, agg);
    gemm_kernel<256, true><<<ggrid, 256>>>(agg, W2, b2, g2, be2, m2, v2, h);

    // ---- layer 3: aggregate h (C=256, no edge weight), GEMM K=256 + bias ----
    gather_kernel<256, false><<<(N_NODES + 3) / 4, 256>>>(h, agg);
    gemm_kernel<256, false><<<ggrid, 256>>>(agg, W3, b3, nullptr, nullptr,
                                            nullptr, nullptr, out);
}

// round 5
// speedup vs baseline: 1.4459x; 1.4459x over previous
#include <cuda_runtime.h>
#include <cuda_bf16.h>

#define N_NODES 50000
#define N_EDGES 1600000
#define C_OUT   256
#define SCAN_BLOCKS 196   // ceil(50000/256)

// ---------------- scratch (static device globals; allocation-free) ----------
__device__ int   g_is64;
__device__ int   g_src[N_EDGES];
__device__ int   g_dst[N_EDGES];
__device__ float g_ew[N_EDGES];
__device__ int   g_srcS[N_EDGES];
__device__ float g_ewS[N_EDGES];
__device__ int   g_deg[N_NODES];
__device__ int   g_blkoff[SCAN_BLOCKS];
__device__ int   g_rowoff[N_NODES + 1];
__device__ int   g_cursor[N_NODES];
__device__ float g_agg[(size_t)N_NODES * C_OUT];
__device__ float g_h[(size_t)N_NODES * C_OUT];

// ---------------- tf32 helpers ----------------------------------------------
__device__ __forceinline__ unsigned f2tf32(float x) {
    unsigned r;
    asm("cvt.rna.tf32.f32 %0, %1;" : "=r"(r) : "f"(x));
    return r;
}

// d += A(16x8 tf32) * B(8x8 tf32), fp32 accumulate
__device__ __forceinline__ void mma_tf32(float c[4], const unsigned a[4],
                                         const unsigned b[2]) {
    asm("mma.sync.aligned.m16n8k8.row.col.f32.tf32.tf32.f32 "
        "{%0,%1,%2,%3}, {%4,%5,%6,%7}, {%8,%9}, {%0,%1,%2,%3};"
        : "+f"(c[0]), "+f"(c[1]), "+f"(c[2]), "+f"(c[3])
        : "r"(a[0]), "r"(a[1]), "r"(a[2]), "r"(a[3]), "r"(b[0]), "r"(b[1]));
}

// ---------------- int64-vs-int32 edge_index detection -----------------------
__global__ void detect_kernel(const int* __restrict__ ei_words) {
    __shared__ int nz;
    if (threadIdx.x == 0) nz = 0;
    __syncthreads();
    if (ei_words[2 * threadIdx.x + 1] != 0) atomicOr(&nz, 1);
    __syncthreads();
    if (threadIdx.x == 0) g_is64 = (nz == 0) ? 1 : 0;
}

// decode edge_index, compute ew = mean(edge_attr, -1), histogram dst degrees
__global__ void build_edges_kernel(const int* __restrict__ ei,
                                   const float* __restrict__ ea) {
    int e = blockIdx.x * blockDim.x + threadIdx.x;
    if (e >= N_EDGES) return;
    int s, d;
    if (g_is64) {
        s = ei[2 * (size_t)e];
        d = ei[2 * (size_t)N_EDGES + 2 * (size_t)e];
    } else {
        s = ei[e];
        d = ei[N_EDGES + e];
    }
    g_src[e] = s;
    g_dst[e] = d;
    const float4* a4 = (const float4*)(ea + (size_t)e * 8);
    float4 u = a4[0];
    float4 v = a4[1];
    g_ew[e] = (u.x + u.y + u.z + u.w + v.x + v.y + v.z + v.w) * 0.125f;
    atomicAdd(&g_deg[d], 1);
}

// ---------------- decoupled 3-phase exclusive scan ---------------------------
__global__ void scan_p1_kernel() {
    int i = blockIdx.x * 256 + threadIdx.x;
    int v = (i < N_NODES) ? g_deg[i] : 0;
#pragma unroll
    for (int o = 16; o > 0; o >>= 1) v += __shfl_down_sync(~0u, v, o);
    __shared__ int ws[8];
    int lane = threadIdx.x & 31, wid = threadIdx.x >> 5;
    if (lane == 0) ws[wid] = v;
    __syncthreads();
    if (threadIdx.x == 0) {
        int s = 0;
#pragma unroll
        for (int w = 0; w < 8; w++) s += ws[w];
        g_blkoff[blockIdx.x] = s;
    }
}

__global__ void scan_p2_kernel() {
    int tid = threadIdx.x;  // 256 threads
    int v = (tid < SCAN_BLOCKS) ? g_blkoff[tid] : 0;
    int lane = tid & 31, wid = tid >> 5;
    int x = v;
#pragma unroll
    for (int o = 1; o < 32; o <<= 1) {
        int t = __shfl_up_sync(~0u, x, o);
        if (lane >= o) x += t;
    }
    __shared__ int ws[8];
    if (lane == 31) ws[wid] = x;
    __syncthreads();
    if (wid == 0 && lane < 8) {
        int w = ws[lane];
#pragma unroll
        for (int o = 1; o < 8; o <<= 1) {
            int t = __shfl_up_sync(0xffu, w, o);
            if (lane >= o) w += t;
        }
        ws[lane] = w;
    }
    __syncthreads();
    int excl = (x - v) + (wid > 0 ? ws[wid - 1] : 0);
    if (tid < SCAN_BLOCKS) g_blkoff[tid] = excl;
    if (tid == 0) g_rowoff[N_NODES] = N_EDGES;
}

__global__ void scan_p3_kernel() {
    int i = blockIdx.x * 256 + threadIdx.x;
    int v = (i < N_NODES) ? g_deg[i] : 0;
    int lane = threadIdx.x & 31, wid = threadIdx.x >> 5;
    int x = v;
#pragma unroll
    for (int o = 1; o < 32; o <<= 1) {
        int t = __shfl_up_sync(~0u, x, o);
        if (lane >= o) x += t;
    }
    __shared__ int ws[8];
    if (lane == 31) ws[wid] = x;
    __syncthreads();
    if (wid == 0 && lane < 8) {
        int w = ws[lane];
#pragma unroll
        for (int o = 1; o < 8; o <<= 1) {
            int t = __shfl_up_sync(0xffu, w, o);
            if (lane >= o) w += t;
        }
        ws[lane] = w;
    }
    __syncthreads();
    int excl = (x - v) + (wid > 0 ? ws[wid - 1] : 0) + g_blkoff[blockIdx.x];
    if (i < N_NODES) {
        g_rowoff[i] = excl;
        g_cursor[i] = excl;
    }
}

// scatter edges into CSR buckets (sorted by dst)
__global__ void fill_kernel() {
    int e = blockIdx.x * blockDim.x + threadIdx.x;
    if (e >= N_EDGES) return;
    int d = g_dst[e];
    int p = atomicAdd(&g_cursor[d], 1);
    g_srcS[p] = g_src[e];
    g_ewS[p] = g_ew[e];
}

// ---------------- gather-aggregate: out[i] = sum_{e: dst=i} in[src_e] * w_e --
template <int C, bool USE_W>
__global__ void gather_kernel(const float* __restrict__ in,
                              float* __restrict__ out) {
    constexpr int L = C / 4;        // lanes per node
    constexpr int G = 256 / L;      // nodes per 256-thread block
    int grp  = threadIdx.x / L;
    int lane = threadIdx.x % L;
    int node = blockIdx.x * G + grp;
    if (node >= N_NODES) return;

    int e0 = g_rowoff[node];
    int e1 = g_rowoff[node + 1];
    const float4* in4 = (const float4*)in;
    float4 acc = make_float4(0.f, 0.f, 0.f, 0.f);

    int e = e0;
    for (; e + 4 <= e1; e += 4) {
        int s0 = g_srcS[e], s1 = g_srcS[e + 1];
        int s2 = g_srcS[e + 2], s3 = g_srcS[e + 3];
        float w0 = USE_W ? g_ewS[e] : 1.0f;
        float w1 = USE_W ? g_ewS[e + 1] : 1.0f;
        float w2 = USE_W ? g_ewS[e + 2] : 1.0f;
        float w3 = USE_W ? g_ewS[e + 3] : 1.0f;
        float4 v0 = in4[(size_t)s0 * L + lane];
        float4 v1 = in4[(size_t)s1 * L + lane];
        float4 v2 = in4[(size_t)s2 * L + lane];
        float4 v3 = in4[(size_t)s3 * L + lane];
        acc.x = fmaf(v0.x, w0, acc.x); acc.y = fmaf(v0.y, w0, acc.y);
        acc.z = fmaf(v0.z, w0, acc.z); acc.w = fmaf(v0.w, w0, acc.w);
        acc.x = fmaf(v1.x, w1, acc.x); acc.y = fmaf(v1.y, w1, acc.y);
        acc.z = fmaf(v1.z, w1, acc.z); acc.w = fmaf(v1.w, w1, acc.w);
        acc.x = fmaf(v2.x, w2, acc.x); acc.y = fmaf(v2.y, w2, acc.y);
        acc.z = fmaf(v2.z, w2, acc.z); acc.w = fmaf(v2.w, w2, acc.w);
        acc.x = fmaf(v3.x, w3, acc.x); acc.y = fmaf(v3.y, w3, acc.y);
        acc.z = fmaf(v3.z, w3, acc.z); acc.w = fmaf(v3.w, w3, acc.w);
    }
    for (; e < e1; e++) {
        int sa = g_srcS[e];
        float wa = USE_W ? g_ewS[e] : 1.0f;
        float4 va = in4[(size_t)sa * L + lane];
        acc.x = fmaf(va.x, wa, acc.x); acc.y = fmaf(va.y, wa, acc.y);
        acc.z = fmaf(va.z, wa, acc.z); acc.w = fmaf(va.w, wa, acc.w);
    }
    ((float4*)out)[(size_t)node * L + lane] = acc;
}

// ---------------- tensor-core GEMM (3xTF32): out = A @ W^T + epilogue -------
// BM=128, BN=64, BK=16, 256 threads = 8 warps (4 m x 2 n), warp tile 32x32.
// Per warp: 2 m-atoms (m16) x 4 n-atoms (n8), mma.m16n8k8 tf32, 3-way split:
//   D += Ah*Bh + Al*Bh + Ah*Bl  (error ~1e-6 rel vs fp32)
template <int K, bool BN_RELU>
__global__ void gemm_tc_kernel(const float* __restrict__ A,
                               const float* __restrict__ W,
                               const float* __restrict__ bias,
                               const float* __restrict__ gam,
                               const float* __restrict__ bet,
                               const float* __restrict__ mu,
                               const float* __restrict__ var,
                               float* __restrict__ out) {
    constexpr int BM = 128, BN = 64, BK = 16;
    constexpr int PK = 20;  // row pitch in words: frag LDS conflict-free
    __shared__ __align__(16) float sAh[BM][PK];
    __shared__ __align__(16) float sAl[BM][PK];
    __shared__ __align__(16) float sBh[BN][PK];
    __shared__ __align__(16) float sBl[BN][PK];

    int m0 = blockIdx.x * BM;
    int n0 = blockIdx.y * BN;
    int tid = threadIdx.x;
    int lane = tid & 31;
    int g = lane >> 2;      // 0..7
    int t = lane & 3;       // 0..3
    int wm = (tid >> 5) & 3;  // warp m index (0..3)
    int wn = tid >> 7;        // warp n index (0..1)

    // loader mapping
    int arow = tid >> 1;            // 0..127
    int akq  = (tid & 1) * 8;       // 0 or 8
    int brow = tid >> 2;            // 0..63
    int bkq  = (tid & 3) * 4;       // 0,4,8,12

    float acc[2][4][4];
#pragma unroll
    for (int i = 0; i < 2; i++)
#pragma unroll
        for (int j = 0; j < 4; j++)
#pragma unroll
            for (int c = 0; c < 4; c++) acc[i][j][c] = 0.f;

    for (int kt = 0; kt < K; kt += BK) {
        // ---- load + split A tile (128 x 16) ----
        {
            float v[8];
            int row = m0 + arow;
            if (row < N_NODES) {
                const float* ap = A + (size_t)row * K + kt + akq;
                float4 u0 = *(const float4*)(ap);
                float4 u1 = *(const float4*)(ap + 4);
                v[0] = u0.x; v[1] = u0.y; v[2] = u0.z; v[3] = u0.w;
                v[4] = u1.x; v[5] = u1.y; v[6] = u1.z; v[7] = u1.w;
            } else {
#pragma unroll
                for (int q = 0; q < 8; q++) v[q] = 0.f;
            }
            float hi[8], lo[8];
#pragma unroll
            for (int q = 0; q < 8; q++) {
                unsigned hu = f2tf32(v[q]);
                hi[q] = __uint_as_float(hu);
                lo[q] = __uint_as_float(f2tf32(v[q] - hi[q]));
            }
            *(float4*)&sAh[arow][akq]     = make_float4(hi[0], hi[1], hi[2], hi[3]);
            *(float4*)&sAh[arow][akq + 4] = make_float4(hi[4], hi[5], hi[6], hi[7]);
            *(float4*)&sAl[arow][akq]     = make_float4(lo[0], lo[1], lo[2], lo[3]);
            *(float4*)&sAl[arow][akq + 4] = make_float4(lo[4], lo[5], lo[6], lo[7]);
        }
        // ---- load + split B tile (64 x 16) : Bs[n][k] = W[n0+n][kt+k] ----
        {
            float4 u = *(const float4*)(W + (size_t)(n0 + brow) * K + kt + bkq);
            float v[4] = {u.x, u.y, u.z, u.w};
            float hi[4], lo[4];
#pragma unroll
            for (int q = 0; q < 4; q++) {
                unsigned hu = f2tf32(v[q]);
                hi[q] = __uint_as_float(hu);
                lo[q] = __uint_as_float(f2tf32(v[q] - hi[q]));
            }
            *(float4*)&sBh[brow][bkq] = make_float4(hi[0], hi[1], hi[2], hi[3]);
            *(float4*)&sBl[brow][bkq] = make_float4(lo[0], lo[1], lo[2], lo[3]);
        }
        __syncthreads();

#pragma unroll
        for (int ko = 0; ko < BK; ko += 8) {
            unsigned ah[2][4], al[2][4], bh[4][2], bl[4][2];
#pragma unroll
            for (int i = 0; i < 2; i++) {
                int rm = wm * 32 + i * 16;
                ah[i][0] = __float_as_uint(sAh[rm + g][ko + t]);
                ah[i][1] = __float_as_uint(sAh[rm + g + 8][ko + t]);
                ah[i][2] = __float_as_uint(sAh[rm + g][ko + t + 4]);
                ah[i][3] = __float_as_uint(sAh[rm + g + 8][ko + t + 4]);
                al[i][0] = __float_as_uint(sAl[rm + g][ko + t]);
                al[i][1] = __float_as_uint(sAl[rm + g + 8][ko + t]);
                al[i][2] = __float_as_uint(sAl[rm + g][ko + t + 4]);
                al[i][3] = __float_as_uint(sAl[rm + g + 8][ko + t + 4]);
            }
#pragma unroll
            for (int j = 0; j < 4; j++) {
                int cn = wn * 32 + j * 8;
                bh[j][0] = __float_as_uint(sBh[cn + g][ko + t]);
                bh[j][1] = __float_as_uint(sBh[cn + g][ko + t + 4]);
                bl[j][0] = __float_as_uint(sBl[cn + g][ko + t]);
                bl[j][1] = __float_as_uint(sBl[cn + g][ko + t + 4]);
            }
#pragma unroll
            for (int i = 0; i < 2; i++)
#pragma unroll
                for (int j = 0; j < 4; j++) {
                    mma_tf32(acc[i][j], ah[i], bh[j]);
                    mma_tf32(acc[i][j], al[i], bh[j]);
                    mma_tf32(acc[i][j], ah[i], bl[j]);
                }
        }
        __syncthreads();
    }

    // ---- epilogue: +bias, optional BN(eval)+ReLU, float2 stores ----
#pragma unroll
    for (int j = 0; j < 4; j++) {
        int n = n0 + wn * 32 + j * 8 + 2 * t;
        float b0 = bias[n], b1 = bias[n + 1];
        float s0 = 0.f, s1 = 0.f, t0 = 0.f, t1 = 0.f;
        if (BN_RELU) {
            s0 = gam[n] * rsqrtf(var[n] + 1e-5f);
            t0 = bet[n] - mu[n] * s0;
            s1 = gam[n + 1] * rsqrtf(var[n + 1] + 1e-5f);
            t1 = bet[n + 1] - mu[n + 1] * s1;
        }
#pragma unroll
        for (int i = 0; i < 2; i++) {
            int r0 = m0 + wm * 32 + i * 16 + g;
            int r1 = r0 + 8;
            float z0 = acc[i][j][0] + b0;
            float z1 = acc[i][j][1] + b1;
            float z2 = acc[i][j][2] + b0;
            float z3 = acc[i][j][3] + b1;
            if (BN_RELU) {
                z0 = fmaxf(fmaf(z0, s0, t0), 0.f);
                z1 = fmaxf(fmaf(z1, s1, t1), 0.f);
                z2 = fmaxf(fmaf(z2, s0, t0), 0.f);
                z3 = fmaxf(fmaf(z3, s1, t1), 0.f);
            }
            if (r0 < N_NODES)
                *(float2*)(out + (size_t)r0 * C_OUT + n) = make_float2(z0, z1);
            if (r1 < N_NODES)
                *(float2*)(out + (size_t)r1 * C_OUT + n) = make_float2(z2, z3);
        }
    }
}

// ---------------- launch ----------------------------------------------------
extern "C" void kernel_launch(void* const* d_in, const int* in_sizes, int n_in,
                              void* d_out, int out_size) {
    const float* x   = (const float*)d_in[0];
    const int*   ei  = (const int*)d_in[1];
    const float* ea  = (const float*)d_in[2];
    const float* W1  = (const float*)d_in[3];
    const float* b1  = (const float*)d_in[4];
    const float* g1  = (const float*)d_in[5];
    const float* be1 = (const float*)d_in[6];
    const float* m1  = (const float*)d_in[7];
    const float* v1  = (const float*)d_in[8];
    const float* W2  = (const float*)d_in[9];
    const float* b2  = (const float*)d_in[10];
    const float* g2  = (const float*)d_in[11];
    const float* be2 = (const float*)d_in[12];
    const float* m2  = (const float*)d_in[13];
    const float* v2  = (const float*)d_in[14];
    const float* W3  = (const float*)d_in[15];
    const float* b3  = (const float*)d_in[16];
    float* out = (float*)d_out;

    void *p_agg, *p_h, *p_deg;
    cudaGetSymbolAddress(&p_agg, g_agg);
    cudaGetSymbolAddress(&p_h, g_h);
    cudaGetSymbolAddress(&p_deg, g_deg);
    float* agg = (float*)p_agg;
    float* h   = (float*)p_h;

    // ---- CSR build (once, reused by all 3 layers) ----
    detect_kernel<<<1, 64>>>(ei);
    cudaMemsetAsync(p_deg, 0, N_NODES * sizeof(int));
    build_edges_kernel<<<(N_EDGES + 255) / 256, 256>>>(ei, ea);
    scan_p1_kernel<<<SCAN_BLOCKS, 256>>>();
    scan_p2_kernel<<<1, 256>>>();
    scan_p3_kernel<<<SCAN_BLOCKS, 256>>>();
    fill_kernel<<<(N_EDGES + 255) / 256, 256>>>();

    dim3 ggrid((N_NODES + 127) / 128, 4);  // 391 x 4, BM=128 BN=64

    // ---- layer 1: aggregate x (C=128), GEMM K=128 + BN1 + ReLU ----
    gather_kernel<128, true><<<(N_NODES + 7) / 8, 256>>>(x, agg);
    gemm_tc_kernel<128, true><<<ggrid, 256>>>(agg, W1, b1, g1, be1, m1, v1, h);

    // ---- layer 2: aggregate h (C=256), GEMM K=256 + BN2 + ReLU ----
    gather_kernel<256, true><<<(N_NODES + 3) / 4, 256>>>(h, agg);
    gemm_tc_kernel<256, true><<<ggrid, 256>>>(agg, W2, b2, g2, be2, m2, v2, h);

    // ---- layer 3: aggregate h (C=256, no edge weight), GEMM K=256 + bias ----
    gather_kernel<256, false><<<(N_NODES + 3) / 4, 256>>>(h, agg);
    gemm_tc_kernel<256, false><<<ggrid, 256>>>(agg, W3, b3, nullptr, nullptr,
                                               nullptr, nullptr, out);
}